// round 6
// baseline (speedup 1.0000x reference)
#include <cuda_runtime.h>
#include <cstddef>

#define K_DIM 2048
#define M_DIM 512
#define N_DIM 64
#define TK    8      // rows per block
#define PB    4      // rows per pass (2 passes)
#define EPS_F 1e-8f
#define GEMM_BLOCKS (K_DIM / TK)   // 256
#define HARD_BLOCKS 4

__device__ unsigned g_hard;

__global__ void reset_kernel() {
    if (threadIdx.x == 0) g_hard = 0u;
}

__device__ __forceinline__ unsigned ld_acq(const unsigned* p) {
    unsigned v;
    asm volatile("ld.acquire.gpu.u32 %0, [%1];" : "=r"(v) : "l"(p) : "memory");
    return v;
}

// ---------------------------------------------------------------------------
// Fused: blocks [0,256) = producer/storer, 8 k-rows in 2 passes of 4.
//   pass: gemm(4 rows, f32x2 FMA) -> softmax -> soft store -> mask/out stores
//   Pass-1 stores drain through L2/DRAM while pass-2 gemm computes.
// Blocks [256,260) = scores_hard (exact multiset 8th-largest), then flag.
// One wave (260 blocks <= 296 slots) -> no deadlock, hard hidden.
// ---------------------------------------------------------------------------
__global__ __launch_bounds__(512, 2)
void fused_kernel(const float* __restrict__ x,
                  const float* __restrict__ w_att,
                  const float* __restrict__ w_b,
                  float* __restrict__ out,
                  float* __restrict__ hard,
                  float* __restrict__ soft,
                  float* __restrict__ mask) {
    const int tid  = threadIdx.x;
    const int lane = tid & 31;
    const int wid  = tid >> 5;

    if (blockIdx.x >= GEMM_BLOCKS) {
        // ---------------- hard path: warp per column n ----------------
        const int n = (blockIdx.x - GEMM_BLOCKS) * 16 + wid;  // 0..63

        float v[16];
#pragma unroll
        for (int jj = 0; jj < 16; jj++)
            v[jj] = w_b[(lane + 32 * jj) * N_DIM + n];

        float t[8];
#pragma unroll
        for (int i = 0; i < 8; i++) t[i] = -3.402823466e38f;
#pragma unroll
        for (int jj = 0; jj < 16; jj++) {
            float val = v[jj];
            if (val > t[7]) {
                t[7] = val;
#pragma unroll
                for (int i = 7; i > 0; i--) {
                    if (t[i] > t[i - 1]) {
                        float tmp = t[i - 1]; t[i - 1] = t[i]; t[i] = tmp;
                    }
                }
            }
        }

        float thr = 0.0f;
#pragma unroll
        for (int it = 0; it < 8; it++) {
            float m = t[0];
#pragma unroll
            for (int o = 16; o; o >>= 1)
                m = fmaxf(m, __shfl_xor_sync(0xffffffffu, m, o));
            unsigned bal = __ballot_sync(0xffffffffu, t[0] == m);
            int src = __ffs(bal) - 1;
            if (lane == src) {
#pragma unroll
                for (int i = 0; i < 7; i++) t[i] = t[i + 1];
                t[7] = -3.402823466e38f;
            }
            thr = m;
        }

#pragma unroll
        for (int jj = 0; jj < 16; jj++) {
            float shv = v[jj] - thr + EPS_F;
            shv = fminf(fmaxf(shv, -1.0f), 1.0f);
            hard[(lane + 32 * jj) * N_DIM + n] = (shv + 1.0f) * 0.5f;
        }
        __syncthreads();
        if (tid == 0) {
            __threadfence();
            atomicAdd(&g_hard, 1u);
        }
        return;
    }

    // ---------------- producer/storer ----------------
    __shared__ __align__(16) float x_sh[TK][M_DIM];     // 16 KB
    __shared__ __align__(16) float soft_sh[PB][M_DIM];  // 8 KB
    __shared__ float red[17];

    const int k0 = blockIdx.x * TK;

    for (int e = tid; e < TK * M_DIM; e += 512) {
        int r = e >> 9;
        int m = e & (M_DIM - 1);
        x_sh[r][m] = x[(size_t)(k0 + r) * M_DIM + m];
    }
    __syncthreads();

    const int j = tid;
    bool hard_ready = false;

#pragma unroll 1
    for (int b = 0; b < TK / PB; b++) {
        const int kp = k0 + b * PB;

        // ---- gemm: 4 rows, packed f32x2 (even/odd-i lanes) ----
        unsigned long long acc2[PB];
#pragma unroll
        for (int r = 0; r < PB; r++) acc2[r] = 0ULL;

        for (int i = 0; i < M_DIM; i += 4) {
            float w0 = w_att[(size_t)(i + 0) * M_DIM + j];
            float w1 = w_att[(size_t)(i + 1) * M_DIM + j];
            float w2 = w_att[(size_t)(i + 2) * M_DIM + j];
            float w3 = w_att[(size_t)(i + 3) * M_DIM + j];
            unsigned long long wp0, wp1;
            asm("mov.b64 %0, {%1, %2};" : "=l"(wp0) : "f"(w0), "f"(w1));
            asm("mov.b64 %0, {%1, %2};" : "=l"(wp1) : "f"(w2), "f"(w3));
#pragma unroll
            for (int r = 0; r < PB; r++) {
                ulonglong2 xp = *(const ulonglong2*)&x_sh[b * PB + r][i];
                asm("fma.rn.f32x2 %0, %1, %2, %0;" : "+l"(acc2[r]) : "l"(xp.x), "l"(wp0));
                asm("fma.rn.f32x2 %0, %1, %2, %0;" : "+l"(acc2[r]) : "l"(xp.y), "l"(wp1));
            }
        }

        float acc[PB];
#pragma unroll
        for (int r = 0; r < PB; r++) {
            float lo, hi;
            asm("mov.b64 {%0, %1}, %2;" : "=f"(lo), "=f"(hi) : "l"(acc2[r]));
            acc[r] = lo + hi;
        }

        // ---- softmax per row over 512 columns ----
#pragma unroll 1
        for (int r = 0; r < PB; r++) {
            float v = acc[r];
#pragma unroll
            for (int o = 16; o; o >>= 1)
                v = fmaxf(v, __shfl_xor_sync(0xffffffffu, v, o));
            if (lane == 0) red[wid] = v;
            __syncthreads();
            if (tid < 32) {
                float w = (lane < 16) ? red[lane] : -3.402823466e38f;
#pragma unroll
                for (int o = 8; o; o >>= 1)
                    w = fmaxf(w, __shfl_xor_sync(0xffffffffu, w, o));
                if (lane == 0) red[16] = w;
            }
            __syncthreads();
            float rowmax = red[16];

            float e = __expf(acc[r] - rowmax);

            v = e;
#pragma unroll
            for (int o = 16; o; o >>= 1)
                v += __shfl_xor_sync(0xffffffffu, v, o);
            if (lane == 0) red[wid] = v;
            __syncthreads();
            if (tid < 32) {
                float w = (lane < 16) ? red[lane] : 0.0f;
#pragma unroll
                for (int o = 8; o; o >>= 1)
                    w += __shfl_xor_sync(0xffffffffu, w, o);
                if (lane == 0) red[16] = w;
            }
            __syncthreads();

            float s = e / red[16] + EPS_F;
            soft_sh[r][j] = s;
            soft[(size_t)(kp + r) * M_DIM + j] = s;
            __syncthreads();
        }

        // ---- gate first store phase on hard completion ----
        if (!hard_ready) {
            if (tid == 0) {
                while (ld_acq(&g_hard) < (unsigned)HARD_BLOCKS) __nanosleep(64);
            }
            __syncthreads();
            hard_ready = true;
        }

        // ---- stores: mask/out for these 4 rows (drain during next pass) ----
        const float4* h4 = (const float4*)hard;
        float4* o4 = (float4*)out  + (size_t)kp * (M_DIM * N_DIM / 4);
        float4* m4 = (float4*)mask + (size_t)kp * (M_DIM * N_DIM / 4);

#pragma unroll 8
        for (int e = tid; e < PB * M_DIM * (N_DIM / 4); e += 512) {
            int inner = e & (M_DIM * N_DIM / 4 - 1);
            int r = e >> 13;
            int m = inner >> 4;
            float4 h = __ldg(&h4[inner]);
            float s  = soft_sh[r][m];
            float p  = s * x_sh[b * PB + r][m];

            float4 mw, o;
            mw.x = h.x * s; mw.y = h.y * s; mw.z = h.z * s; mw.w = h.w * s;
            o.x  = h.x * p; o.y  = h.y * p; o.z  = h.z * p; o.w  = h.w * p;

            __stcs(&m4[e], mw);
            __stcs(&o4[e], o);
        }
        // no __syncthreads needed here: soft_sh rewritten only after the
        // next pass's softmax syncs; x_sh rows disjoint per pass... but
        // soft_sh IS reused next pass -> sync before overwrite:
        __syncthreads();
    }
}

// ---------------------------------------------------------------------------
// d_out layout (reference return order):
//   out         [K,M,N] : offset 0           (67,108,864)
//   scores_hard [M,N]   : offset 67,108,864  (32,768)
//   scores_soft [K,M]   : offset 67,141,632  (1,048,576)
//   mask_weight [K,M,N] : offset 68,190,208  (67,108,864)
// ---------------------------------------------------------------------------
extern "C" void kernel_launch(void* const* d_in, const int* in_sizes, int n_in,
                              void* d_out, int out_size) {
    const float* x     = (const float*)d_in[0];
    const float* w_att = (const float*)d_in[1];
    const float* w_b   = (const float*)d_in[2];

    float* out  = (float*)d_out;
    float* hard = out + 67108864ULL;
    float* soft = out + 67141632ULL;
    float* mask = out + 68190208ULL;

    reset_kernel<<<1, 32>>>();
    fused_kernel<<<GEMM_BLOCKS + HARD_BLOCKS, 512>>>(
        x, w_att, w_b, out, hard, soft, mask);
}

// round 7
// speedup vs baseline: 1.1940x; 1.1940x over previous
#include <cuda_runtime.h>
#include <cstddef>

#define K_DIM 2048
#define M_DIM 512
#define N_DIM 64
#define TK    16     // rows per gemm block
#define EPS_F 1e-8f
#define GEMM_BLOCKS (K_DIM / TK)   // 128
#define HARD_BLOCKS 4              // warp-per-column, 64 cols

// ---------------------------------------------------------------------------
// Kernel 1: blocks [0,128) = GEMM(x@w_att)+softmax -> soft [K,M].
//   TK=16 rows/block, FFMA2 packed accumulate, 2-deep w_att prefetch,
//   warp-parallel softmax (warp w owns row w).
// Blocks [128,132) = scores_hard (exact multiset 8th-largest of w_b cols).
// ---------------------------------------------------------------------------
__global__ __launch_bounds__(512, 1)
void gemm_softmax_hard_kernel(const float* __restrict__ x,
                              const float* __restrict__ w_att,
                              const float* __restrict__ w_b,
                              float* __restrict__ soft_out,
                              float* __restrict__ hard_out) {
    const int tid  = threadIdx.x;
    const int lane = tid & 31;
    const int wid  = tid >> 5;

    if (blockIdx.x >= GEMM_BLOCKS) {
        // ---------------- hard path: warp per column n ----------------
        const int n = (blockIdx.x - GEMM_BLOCKS) * 16 + wid;  // 0..63

        float v[16];
#pragma unroll
        for (int jj = 0; jj < 16; jj++)
            v[jj] = w_b[(lane + 32 * jj) * N_DIM + n];

        float t[8];
#pragma unroll
        for (int i = 0; i < 8; i++) t[i] = -3.402823466e38f;
#pragma unroll
        for (int jj = 0; jj < 16; jj++) {
            float val = v[jj];
            if (val > t[7]) {
                t[7] = val;
#pragma unroll
                for (int i = 7; i > 0; i--) {
                    if (t[i] > t[i - 1]) {
                        float tmp = t[i - 1]; t[i - 1] = t[i]; t[i] = tmp;
                    }
                }
            }
        }

        float thr = 0.0f;
#pragma unroll
        for (int it = 0; it < 8; it++) {
            float m = t[0];
#pragma unroll
            for (int o = 16; o; o >>= 1)
                m = fmaxf(m, __shfl_xor_sync(0xffffffffu, m, o));
            unsigned bal = __ballot_sync(0xffffffffu, t[0] == m);
            int src = __ffs(bal) - 1;
            if (lane == src) {
#pragma unroll
                for (int i = 0; i < 7; i++) t[i] = t[i + 1];
                t[7] = -3.402823466e38f;
            }
            thr = m;
        }

#pragma unroll
        for (int jj = 0; jj < 16; jj++) {
            float shv = v[jj] - thr + EPS_F;
            shv = fminf(fmaxf(shv, -1.0f), 1.0f);
            hard_out[(lane + 32 * jj) * N_DIM + n] = (shv + 1.0f) * 0.5f;
        }
        return;
    }

    // ---------------- gemm + softmax path ----------------
    // sh: first holds x rows [TK][512]; after gemm, reused (transposed) for
    // the accumulators so each warp can reduce one row independently.
    __shared__ __align__(16) float sh[TK * M_DIM];  // 32 KB

    const int k0 = blockIdx.x * TK;

    // load 16 x-rows (float4, coalesced)
    {
        const float4* xs4 = (const float4*)(x + (size_t)k0 * M_DIM);
        float4* sh4 = (float4*)sh;
#pragma unroll
        for (int e = 0; e < TK * M_DIM / 4 / 512; e++)
            sh4[tid + e * 512] = xs4[tid + e * 512];
    }
    __syncthreads();

    // packed accumulators: lane0 = even-i partial, lane1 = odd-i partial
    unsigned long long acc2[TK];
#pragma unroll
    for (int r = 0; r < TK; r++) acc2[r] = 0ULL;

    const int j = tid;
    const float* wcol = w_att + j;

    // 2-deep prefetch pipeline over i (4 i-values per stage)
    float c0 = wcol[(size_t)0 * M_DIM], c1 = wcol[(size_t)1 * M_DIM];
    float c2 = wcol[(size_t)2 * M_DIM], c3 = wcol[(size_t)3 * M_DIM];
    float n0 = wcol[(size_t)4 * M_DIM], n1 = wcol[(size_t)5 * M_DIM];
    float n2 = wcol[(size_t)6 * M_DIM], n3 = wcol[(size_t)7 * M_DIM];

#pragma unroll 1
    for (int i = 0; i < M_DIM; i += 4) {
        const float* wn = wcol + (size_t)((i + 8) & (M_DIM - 1)) * M_DIM;
        float p0 = wn[(size_t)0 * M_DIM];
        float p1 = wn[(size_t)1 * M_DIM];
        float p2 = wn[(size_t)2 * M_DIM];
        float p3 = wn[(size_t)3 * M_DIM];

        unsigned long long wp0, wp1;
        asm("mov.b64 %0, {%1, %2};" : "=l"(wp0) : "f"(c0), "f"(c1));
        asm("mov.b64 %0, {%1, %2};" : "=l"(wp1) : "f"(c2), "f"(c3));
#pragma unroll
        for (int r = 0; r < TK; r++) {
            ulonglong2 xp = *(const ulonglong2*)&sh[r * M_DIM + i];
            asm("fma.rn.f32x2 %0, %1, %2, %0;" : "+l"(acc2[r]) : "l"(xp.x), "l"(wp0));
            asm("fma.rn.f32x2 %0, %1, %2, %0;" : "+l"(acc2[r]) : "l"(xp.y), "l"(wp1));
        }
        c0 = n0; c1 = n1; c2 = n2; c3 = n3;
        n0 = p0; n1 = p1; n2 = p2; n3 = p3;
    }

    float acc[TK];
#pragma unroll
    for (int r = 0; r < TK; r++) {
        float lo, hi;
        asm("mov.b64 {%0, %1}, %2;" : "=f"(lo), "=f"(hi) : "l"(acc2[r]));
        acc[r] = lo + hi;
    }

    // transpose accumulators into shared: sh[r*512 + j] = acc[r]
    __syncthreads();   // done reading x from sh
#pragma unroll
    for (int r = 0; r < TK; r++) sh[r * M_DIM + j] = acc[r];
    __syncthreads();

    // warp w reduces row w (16 warps, 16 rows) — fully parallel
    {
        const float* row = sh + wid * M_DIM;
        float v[16];
#pragma unroll
        for (int t = 0; t < 16; t++) v[t] = row[lane + 32 * t];

        float mx = v[0];
#pragma unroll
        for (int t = 1; t < 16; t++) mx = fmaxf(mx, v[t]);
#pragma unroll
        for (int o = 16; o; o >>= 1)
            mx = fmaxf(mx, __shfl_xor_sync(0xffffffffu, mx, o));

        float sum = 0.0f;
#pragma unroll
        for (int t = 0; t < 16; t++) {
            v[t] = __expf(v[t] - mx);
            sum += v[t];
        }
#pragma unroll
        for (int o = 16; o; o >>= 1)
            sum += __shfl_xor_sync(0xffffffffu, sum, o);

        float inv = 1.0f / sum;
        float* so = soft_out + (size_t)(k0 + wid) * M_DIM;
#pragma unroll
        for (int t = 0; t < 16; t++)
            so[lane + 32 * t] = v[t] * inv + EPS_F;
    }
}

// ---------------------------------------------------------------------------
// Kernel 2: bcast (unchanged from R4, proven 74.9% DRAM).
//   mask[k,m,n] = hard[m,n]*soft[k,m];  out[k,m,n] = mask*x[k,m]
// ---------------------------------------------------------------------------
__global__ __launch_bounds__(512)
void bcast_kernel(const float* __restrict__ x,
                  const float* __restrict__ soft,
                  const float* __restrict__ hard,
                  float* __restrict__ out,
                  float* __restrict__ mask) {
    __shared__ float s_sh[M_DIM];
    __shared__ float p_sh[M_DIM];

    const int k = blockIdx.x;
    {
        int m = threadIdx.x;
        float s  = soft[(size_t)k * M_DIM + m];
        float xv = x[(size_t)k * M_DIM + m];
        s_sh[m] = s;
        p_sh[m] = s * xv;
    }
    __syncthreads();

    const float4* h4 = (const float4*)hard;
    float4* o4 = (float4*)out  + (size_t)k * (M_DIM * N_DIM / 4);
    float4* m4 = (float4*)mask + (size_t)k * (M_DIM * N_DIM / 4);

#pragma unroll 8
    for (int e = threadIdx.x; e < M_DIM * N_DIM / 4; e += 512) {
        int m = e >> 4;
        float4 h = h4[e];
        float s = s_sh[m];
        float p = p_sh[m];

        float4 mw, o;
        mw.x = h.x * s; mw.y = h.y * s; mw.z = h.z * s; mw.w = h.w * s;
        o.x  = h.x * p; o.y  = h.y * p; o.z  = h.z * p; o.w  = h.w * p;

        __stcs(&m4[e], mw);
        __stcs(&o4[e], o);
    }
}

// ---------------------------------------------------------------------------
// d_out layout (reference return order):
//   out         [K,M,N] : offset 0           (67,108,864)
//   scores_hard [M,N]   : offset 67,108,864  (32,768)
//   scores_soft [K,M]   : offset 67,141,632  (1,048,576)
//   mask_weight [K,M,N] : offset 68,190,208  (67,108,864)
// ---------------------------------------------------------------------------
extern "C" void kernel_launch(void* const* d_in, const int* in_sizes, int n_in,
                              void* d_out, int out_size) {
    const float* x     = (const float*)d_in[0];
    const float* w_att = (const float*)d_in[1];
    const float* w_b   = (const float*)d_in[2];

    float* out  = (float*)d_out;
    float* hard = out + 67108864ULL;
    float* soft = out + 67141632ULL;
    float* mask = out + 68190208ULL;

    gemm_softmax_hard_kernel<<<GEMM_BLOCKS + HARD_BLOCKS, 512>>>(
        x, w_att, w_b, soft, hard);
    bcast_kernel<<<K_DIM, 512>>>(x, soft, hard, out, mask);
}